// round 5
// baseline (speedup 1.0000x reference)
#include <cuda_runtime.h>
#include <cuda_bf16.h>
#include <cstdint>

// ---------------------------------------------------------------------------
// Speculative-decode cache-loc compaction.
//   span[b]      = accept_length[b] + 1
//   old_start[b] = exclusive_cumsum(span)[b]
//   new_start[b] = exclusive_cumsum(accept_length_filter)[b]
//   out[new_start[b] + i] = tgt_cache_loc[old_start[b] + i],  i < filter[b]
//
// Kernel 1: single-pass decoupled-lookback scan; emits per-batch inclusive
//           filter-cumsum (g_cum), src-shift (g_shift), and a dense map from
//           512-element output chunks to their starting batch (g_chunk_b0).
// Kernel 2: flat output-indexed copy — 1 thread per 4 outputs, aligned
//           float4 stores, chunk map kills the batch search.
// ---------------------------------------------------------------------------

#define MAXB (1 << 17)
#define SCAN_BLK 1024
#define MAX_TILES 128            // MAXB / SCAN_BLK
#define MAX_CHUNKS (1 << 17)     // out_size < 2^26 / 512

// Packed tile state: [61:60] flag (0=invalid, 1=aggregate, 2=inclusive),
//                    [59:30] span sum, [29:0] filter sum.
__device__ unsigned long long g_tile_state[MAX_TILES];  // zero-init at load
__device__ unsigned int g_done;                         // zero-init at load
__device__ int g_cum[MAXB];        // inclusive cumsum of accept_length_filter
__device__ int g_shift[MAXB];      // old_start[b] - new_start[b]
__device__ int g_chunk_b0[MAX_CHUNKS];  // first batch covering chunk k

__device__ __forceinline__ int warp_incl_scan(int v, int lane) {
    #pragma unroll
    for (int off = 1; off < 32; off <<= 1) {
        int n = __shfl_up_sync(0xFFFFFFFFu, v, off);
        if (lane >= off) v += n;
    }
    return v;
}

__device__ __forceinline__ unsigned long long pack_state(unsigned long long flag,
                                                         int s, int f) {
    return (flag << 60) | ((unsigned long long)(unsigned)s << 30)
         | (unsigned long long)(unsigned)f;
}

// ---- kernel 1: fused single-pass scan -------------------------------------
__global__ void __launch_bounds__(SCAN_BLK)
k_scan_fused(const int* __restrict__ al, const int* __restrict__ alf, int B) {
    const int tid = threadIdx.x;
    const int tile = blockIdx.x;
    const int i = tile * SCAN_BLK + tid;
    const int lane = tid & 31, wid = tid >> 5;

    int s = 0, f = 0;
    if (i < B) { s = al[i] + 1; f = alf[i]; }

    int incl_s = warp_incl_scan(s, lane);
    int incl_f = warp_incl_scan(f, lane);

    __shared__ int ws[32], wf[32], wso[32], wfo[32];
    __shared__ int sh_tot[2];
    __shared__ int sh_ex[2];
    if (lane == 31) { ws[wid] = incl_s; wf[wid] = incl_f; }
    __syncthreads();
    if (wid == 0) {
        int vs = ws[lane], vf = wf[lane];
        int is  = warp_incl_scan(vs, lane);
        int iff = warp_incl_scan(vf, lane);
        wso[lane] = is - vs;
        wfo[lane] = iff - vf;
        if (lane == 31) { sh_tot[0] = is; sh_tot[1] = iff; }
    }
    __syncthreads();
    const int ts = sh_tot[0], tf = sh_tot[1];

    // warp 0: publish aggregate, decoupled lookback, publish inclusive
    if (wid == 0) {
        if (lane == 0)
            atomicExch(&g_tile_state[tile], pack_state(1ULL, ts, tf));

        int es = 0, ef = 0;
        int idx = tile - 1;
        while (idx >= 0) {
            int p = idx - lane;
            bool active = (p >= 0);
            unsigned long long st = 0;
            if (active) {
                do {
                    st = *(volatile unsigned long long*)&g_tile_state[p];
                } while ((st >> 60) == 0ULL);
            }
            unsigned incl_mask =
                __ballot_sync(0xFFFFFFFFu, active && ((st >> 60) == 2ULL));
            int L = incl_mask ? (__ffs(incl_mask) - 1) : 32;
            int cs = 0, cf = 0;
            if (active && lane <= L) {
                cs = (int)((st >> 30) & 0x3FFFFFFFULL);
                cf = (int)(st & 0x3FFFFFFFULL);
            }
            #pragma unroll
            for (int o = 16; o > 0; o >>= 1) {
                cs += __shfl_xor_sync(0xFFFFFFFFu, cs, o);
                cf += __shfl_xor_sync(0xFFFFFFFFu, cf, o);
            }
            es += cs; ef += cf;
            if (L < 32) break;
            idx -= 32;
        }
        if (lane == 0) {
            atomicExch(&g_tile_state[tile], pack_state(2ULL, es + ts, ef + tf));
            sh_ex[0] = es; sh_ex[1] = ef;
        }
    }
    __syncthreads();
    const int es = sh_ex[0], ef = sh_ex[1];

    if (i < B) {
        int ns = ef + (incl_f - f) + wfo[wid];         // new_start (exclusive)
        int os = es + (incl_s - s) + wso[wid];         // old_start (exclusive)
        g_cum[i] = ns + f;                              // inclusive filter cumsum
        g_shift[i] = os - ns;
        if (f > 0) {
            // mark every 512-aligned output-chunk start inside [ns, ns+f)
            int k0 = (ns + 511) >> 9;
            int k1 = (ns + f - 1) >> 9;
            for (int k = k0; k <= k1; k++) g_chunk_b0[k] = i;
        }
    }

    // Reset tile state for the next graph-replayed launch (counted: safe).
    if (tid == 0) {
        __threadfence();
        unsigned pos = atomicAdd(&g_done, 1u);
        if (pos == gridDim.x - 1) {
            for (int t2 = 0; t2 < (int)gridDim.x; t2++)
                g_tile_state[t2] = 0ULL;
            __threadfence();
            g_done = 0;
        }
    }
}

// ---- kernel 2: flat output-indexed copy -----------------------------------
// 1 thread = 4 consecutive outputs. 1 block (128 thr) = one 512-elem chunk.
__global__ void __launch_bounds__(128)
k_copy_flat(const float* __restrict__ src, float* __restrict__ out,
            int out_size) {
    int j0 = (blockIdx.x << 9) | (threadIdx.x << 2);
    if (j0 >= out_size) return;

    int b = __ldg(&g_chunk_b0[blockIdx.x]);     // broadcast within block
    while (__ldg(&g_cum[b]) <= j0) b++;         // avg ~1 L1-hot step
    int c = __ldg(&g_cum[b]);

    if (j0 + 4 <= out_size && c >= j0 + 4) {
        // fast path (~99%): all 4 elements in one batch
        const float* sp = src + j0 + __ldg(&g_shift[b]);
        float4 v;
        v.x = __ldg(sp + 0);
        v.y = __ldg(sp + 1);
        v.z = __ldg(sp + 2);
        v.w = __ldg(sp + 3);
        *reinterpret_cast<float4*>(out + j0) = v;   // 16B-aligned by construction
    } else {
        #pragma unroll
        for (int e = 0; e < 4; e++) {
            int j = j0 + e;
            if (j >= out_size) break;
            while (__ldg(&g_cum[b]) <= j) b++;
            out[j] = __ldg(&src[j + __ldg(&g_shift[b])]);
        }
    }
}

// ---------------------------------------------------------------------------
extern "C" void kernel_launch(void* const* d_in, const int* in_sizes, int n_in,
                              void* d_out, int out_size) {
    const float* tgt = (const float*)d_in[0];
    const int* al  = (const int*)d_in[1];
    const int* alf = (const int*)d_in[2];
    float* out = (float*)d_out;

    int B = in_sizes[1];
    int ntiles = (B + SCAN_BLK - 1) / SCAN_BLK;   // 64 for B=65536

    k_scan_fused<<<ntiles, SCAN_BLK>>>(al, alf, B);

    if (out_size > 0) {
        int nchunks = (out_size + 511) >> 9;
        k_copy_flat<<<nchunks, 128>>>(tgt, out, out_size);
    }
}

// round 6
// speedup vs baseline: 1.2882x; 1.2882x over previous
#include <cuda_runtime.h>
#include <cuda_bf16.h>
#include <cstdint>

// ---------------------------------------------------------------------------
// Speculative-decode cache-loc compaction.
//   span[b]      = accept_length[b] + 1
//   old_start[b] = exclusive_cumsum(span)[b]
//   new_start[b] = exclusive_cumsum(accept_length_filter)[b]
//   out[new_start[b] + i] = tgt_cache_loc[old_start[b] + i],  i < filter[b]
//
// Kernel 1: single-pass decoupled-lookback scan -> g_meta[b]={os,ns,len,0}.
// Kernel 2: warp-per-batch copy, 4-deep unrolled scalar loads (MLP=4).
// ---------------------------------------------------------------------------

#define MAXB (1 << 17)
#define SCAN_BLK 1024
#define MAX_TILES 128            // MAXB / SCAN_BLK

// Packed tile state: [61:60] flag (0=invalid, 1=aggregate, 2=inclusive),
//                    [59:30] span sum, [29:0] filter sum.
__device__ unsigned long long g_tile_state[MAX_TILES];  // zero-init at load
__device__ unsigned int g_done;                         // zero-init at load
__device__ int4 g_meta[MAXB];    // {old_start, new_start, len, 0}

__device__ __forceinline__ int warp_incl_scan(int v, int lane) {
    #pragma unroll
    for (int off = 1; off < 32; off <<= 1) {
        int n = __shfl_up_sync(0xFFFFFFFFu, v, off);
        if (lane >= off) v += n;
    }
    return v;
}

__device__ __forceinline__ unsigned long long pack_state(unsigned long long flag,
                                                         int s, int f) {
    return (flag << 60) | ((unsigned long long)(unsigned)s << 30)
         | (unsigned long long)(unsigned)f;
}

// ---- kernel 1: fused single-pass scan -------------------------------------
__global__ void __launch_bounds__(SCAN_BLK)
k_scan_fused(const int* __restrict__ al, const int* __restrict__ alf, int B) {
    const int tid = threadIdx.x;
    const int tile = blockIdx.x;
    const int i = tile * SCAN_BLK + tid;
    const int lane = tid & 31, wid = tid >> 5;

    int s = 0, f = 0;
    if (i < B) { s = al[i] + 1; f = alf[i]; }

    int incl_s = warp_incl_scan(s, lane);
    int incl_f = warp_incl_scan(f, lane);

    __shared__ int ws[32], wf[32], wso[32], wfo[32];
    __shared__ int sh_tot[2];
    __shared__ int sh_ex[2];
    if (lane == 31) { ws[wid] = incl_s; wf[wid] = incl_f; }
    __syncthreads();
    if (wid == 0) {
        int vs = ws[lane], vf = wf[lane];
        int is  = warp_incl_scan(vs, lane);
        int iff = warp_incl_scan(vf, lane);
        wso[lane] = is - vs;
        wfo[lane] = iff - vf;
        if (lane == 31) { sh_tot[0] = is; sh_tot[1] = iff; }
    }
    __syncthreads();
    const int ts = sh_tot[0], tf = sh_tot[1];

    // warp 0: publish aggregate, decoupled lookback, publish inclusive
    if (wid == 0) {
        if (lane == 0)
            atomicExch(&g_tile_state[tile], pack_state(1ULL, ts, tf));

        int es = 0, ef = 0;
        int idx = tile - 1;
        while (idx >= 0) {
            int p = idx - lane;
            bool active = (p >= 0);
            unsigned long long st = 0;
            if (active) {
                do {
                    st = *(volatile unsigned long long*)&g_tile_state[p];
                } while ((st >> 60) == 0ULL);
            }
            unsigned incl_mask =
                __ballot_sync(0xFFFFFFFFu, active && ((st >> 60) == 2ULL));
            int L = incl_mask ? (__ffs(incl_mask) - 1) : 32;
            int cs = 0, cf = 0;
            if (active && lane <= L) {
                cs = (int)((st >> 30) & 0x3FFFFFFFULL);
                cf = (int)(st & 0x3FFFFFFFULL);
            }
            #pragma unroll
            for (int o = 16; o > 0; o >>= 1) {
                cs += __shfl_xor_sync(0xFFFFFFFFu, cs, o);
                cf += __shfl_xor_sync(0xFFFFFFFFu, cf, o);
            }
            es += cs; ef += cf;
            if (L < 32) break;
            idx -= 32;
        }
        if (lane == 0) {
            atomicExch(&g_tile_state[tile], pack_state(2ULL, es + ts, ef + tf));
            sh_ex[0] = es; sh_ex[1] = ef;
        }
    }
    __syncthreads();
    const int es = sh_ex[0], ef = sh_ex[1];

    if (i < B) {
        int os = es + (incl_s - s) + wso[wid];   // old_start
        int ns = ef + (incl_f - f) + wfo[wid];   // new_start
        g_meta[i] = make_int4(os, ns, f, 0);
    }

    // Reset tile state for the next graph-replayed launch. Each block counts
    // in only AFTER its lookback completed, so when the count hits gridDim.x
    // no block will read g_tile_state again this launch.
    if (tid == 0) {
        __threadfence();
        unsigned pos = atomicAdd(&g_done, 1u);
        if (pos == gridDim.x - 1) {
            for (int t2 = 0; t2 < (int)gridDim.x; t2++)
                g_tile_state[t2] = 0ULL;
            __threadfence();
            g_done = 0;
        }
    }
}

// ---- kernel 2: warp-per-batch copy, 4-deep unrolled -----------------------
__global__ void __launch_bounds__(256)
k_copy(const float* __restrict__ src, float* __restrict__ out, int B) {
    int gwarp = (blockIdx.x * blockDim.x + threadIdx.x) >> 5;
    int lane = threadIdx.x & 31;
    if (gwarp >= B) return;

    int4 m = __ldg(&g_meta[gwarp]);         // one broadcast LDG.128 per warp
    int len = m.z;
    if (len == 0) return;
    const float* __restrict__ s = src + m.x;
    float* __restrict__ d = out + m.y;

    int i = lane;
    // main: 4 independent coalesced loads per lane per iteration (MLP=4)
    for (; i + 96 < len; i += 128) {
        float a0 = __ldg(s + i);
        float a1 = __ldg(s + i + 32);
        float a2 = __ldg(s + i + 64);
        float a3 = __ldg(s + i + 96);
        d[i]      = a0;
        d[i + 32] = a1;
        d[i + 64] = a2;
        d[i + 96] = a3;
    }
    // remainder
    for (; i < len; i += 32)
        d[i] = __ldg(s + i);
}

// ---------------------------------------------------------------------------
extern "C" void kernel_launch(void* const* d_in, const int* in_sizes, int n_in,
                              void* d_out, int out_size) {
    const float* tgt = (const float*)d_in[0];
    const int* al  = (const int*)d_in[1];
    const int* alf = (const int*)d_in[2];
    float* out = (float*)d_out;

    int B = in_sizes[1];
    int ntiles = (B + SCAN_BLK - 1) / SCAN_BLK;   // 64 for B=65536

    k_scan_fused<<<ntiles, SCAN_BLK>>>(al, alf, B);

    long long total_threads = (long long)B * 32;
    int tpb = 256;
    int cblocks = (int)((total_threads + tpb - 1) / tpb);
    k_copy<<<cblocks, tpb>>>(tgt, out, B);
}